// round 15
// baseline (speedup 1.0000x reference)
#include <cuda_runtime.h>
#include <cstdint>

#define Bn 16
#define Cn 19
#define Hn 512
#define Wn 512
#define HWn (Hn * Wn)          // 262144
#define NPIX (Bn * HWn)        // 4194304
#define TPB 512                // one thread per pixel of one row
#define NBLK (Bn * Hn)         // 8192 blocks = one row each
#define ROW_BYTES (Wn * 4)     // 2048 B per channel row
#define TX_BYTES (Cn * ROW_BYTES)  // 38912 B per block

__device__ double g_acc;       // zero at load; reset by last block each call
__device__ unsigned g_done;    // zero at load; reset by last block each call

__device__ __forceinline__ uint32_t smem_u32(const void* p) {
    uint32_t a;
    asm("{ .reg .u64 t; cvta.to.shared.u64 t, %1; cvt.u32.u64 %0, t; }"
        : "=r"(a) : "l"(p));
    return a;
}

// bulk async copy global->shared, completion via mbarrier transaction bytes
__device__ __forceinline__ void bulk_g2s(uint32_t dst, const void* src,
                                         uint32_t bytes, uint32_t mbar) {
    asm volatile(
        "cp.async.bulk.shared::cluster.global.mbarrier::complete_tx::bytes "
        "[%0], [%1], %2, [%3];"
        :: "r"(dst), "l"(src), "r"(bytes), "r"(mbar) : "memory");
}

// STRIDE compile-time: 2 = int64 targets (read low word), 1 = int32.
template <int STRIDE>
__device__ __forceinline__ bool edge_test(const int* __restrict__ tg,
                                          int b, int h, int w, int& c0) {
    const int* tc = tg + (size_t)(b * HWn + h * Wn + w) * STRIDE;
    c0 = __ldg(tc);
    int d = 0;
    if (h > 0 && h < Hn - 1 && w > 0 && w < Wn - 1) {
#pragma unroll
        for (int dy = -1; dy <= 1; dy++)
#pragma unroll
            for (int dx = -1; dx <= 1; dx++) {
                if (dy == 0 && dx == 0) continue;
                d |= (__ldg(tc + (dy * Wn + dx) * STRIDE) ^ c0);
            }
    } else {
#pragma unroll
        for (int dy = -1; dy <= 1; dy++)
#pragma unroll
            for (int dx = -1; dx <= 1; dx++) {
                if (dy == 0 && dx == 0) continue;
                int hh = h + dy, ww = w + dx;
                if (hh >= 0 && hh < Hn && ww >= 0 && ww < Wn)
                    d |= (__ldg(tc + (dy * Wn + dx) * STRIDE) ^ c0);
            }
    }
    return d != 0;
}

__global__ void __launch_bounds__(TPB, 4)
edgeloss_bulk(const float* __restrict__ pred,
              const unsigned int* __restrict__ tg_raw,
              float* __restrict__ out) {
    const unsigned FULL = 0xFFFFFFFFu;
    __shared__ __align__(128) float s_pred[Cn * Wn];   // 38 KB
    __shared__ __align__(8) unsigned long long s_mbar;
    __shared__ int s_is64;
    __shared__ float s_warp[TPB / 32];

    const int tid = threadIdx.x;
    const uint32_t mbar = smem_u32(&s_mbar);

    // dtype detect: warp 0 checks 64 word-pairs; int32 false-positive p=(1/19)^64
    if (tid < 32) {
        bool ok = true;
#pragma unroll
        for (int k = 0; k < 2; k++) {
            int i = tid + 32 * k;
            ok &= (__ldg(&tg_raw[2 * i + 1]) == 0u) && (__ldg(&tg_raw[2 * i]) < 19u);
        }
        int all_ok = __all_sync(FULL, ok);
        if (tid == 0) s_is64 = all_ok;
    }
    if (tid == 0) {
        asm volatile("mbarrier.init.shared.b64 [%0], %1;"
                     :: "r"(mbar), "r"(1u) : "memory");
    }
    __syncthreads();   // mbarrier init + s_is64 visible

    const int b = blockIdx.x >> 9;          // / Hn
    const int h = blockIdx.x & (Hn - 1);
    const int w = tid;

    // one thread launches the whole block's prediction traffic: 19 x 2KB bulk
    // copies. DMA engine keeps LTS/DRAM queues full with zero warp scoreboard
    // involvement; other resident blocks compute meanwhile.
    if (tid == 0) {
        asm volatile("mbarrier.arrive.expect_tx.shared.b64 _, [%0], %1;"
                     :: "r"(mbar), "r"((uint32_t)TX_BYTES) : "memory");
        const uint32_t dst0 = smem_u32(s_pred);
        const float* src0 = pred + ((size_t)b * Cn) * HWn + (size_t)h * Wn;
#pragma unroll
        for (int c = 0; c < Cn; c++)
            bulk_g2s(dst0 + c * ROW_BYTES, src0 + (size_t)c * HWn,
                     ROW_BYTES, mbar);
    }

    // edge mask from targets while the bulk copies fly (L1/L2-hot loads)
    const int* tg = (const int*)tg_raw;
    int c0;
    bool edge;
    if (s_is64) edge = edge_test<2>(tg, b, h, w, c0);
    else        edge = edge_test<1>(tg, b, h, w, c0);

    // wait for prediction row data (acquire orders the smem reads below)
    {
        uint32_t done;
        asm volatile(
            "{\n\t.reg .pred p;\n\t"
            "mbarrier.try_wait.parity.acquire.cta.shared::cta.b64 p, [%1], %2;\n\t"
            "selp.b32 %0, 1, 0, p;\n\t}"
            : "=r"(done) : "r"(mbar), "r"(0u) : "memory");
        if (!done) {
            asm volatile(
                "{\n\t.reg .pred P1;\n\t"
                "WL_%=:\n\t"
                "mbarrier.try_wait.parity.acquire.cta.shared::cta.b64 P1, [%0], %1, 0x989680;\n\t"
                "@P1 bra.uni WD_%=;\n\t"
                "bra.uni WL_%=;\n\t"
                "WD_%=:\n\t}"
                :: "r"(mbar), "r"(0u) : "memory");
        }
    }

    // logsumexp from smem: conflict-free LDS (bank = w%32 for every channel)
    float s0 = 0.0f, s1 = 0.0f;
#pragma unroll
    for (int c = 0; c < Cn; c++) {
        float x = s_pred[c * Wn + w];
        if (c & 1) s1 += __expf(x); else s0 += __expf(x);
    }
    const float xt = s_pred[c0 * Wn + w];   // dynamic index: 1 LDS, no conflicts

    float ce = __logf(s0 + s1) - xt;
    float val = edge ? (2.0f * ce) : ce;

    // block reduce (16 warps)
#pragma unroll
    for (int off = 16; off > 0; off >>= 1)
        val += __shfl_down_sync(FULL, val, off);
    int lane = tid & 31;
    int wid = tid >> 5;
    if (lane == 0) s_warp[wid] = val;
    __syncthreads();
    if (wid == 0) {
        float bs = (lane < TPB / 32) ? s_warp[lane] : 0.0f;
#pragma unroll
        for (int off = 8; off > 0; off >>= 1)
            bs += __shfl_down_sync(FULL, bs, off);
        if (lane == 0) {
            // FENCE-FREE ordering (no CCTL.IVALL L1 flush): atomics perform at
            // L2; register data-dependence orders g_acc-add before g_done-inc.
            double old = atomicAdd(&g_acc, (double)bs);
            unsigned dep = (unsigned)__double2loint(old);
            asm volatile("and.b32 %0, %0, 0;" : "+r"(dep));  // opaque zero
            unsigned done = atomicAdd(&g_done, 1u + dep);
            if (done == NBLK - 1) {
                double total = atomicAdd(&g_acc, 0.0);
                out[0] = (float)(total / (double)NPIX);
                g_acc = 0.0;               // reset for next graph replay
                g_done = 0u;
            }
        }
    }
}

extern "C" void kernel_launch(void* const* d_in, const int* in_sizes, int n_in,
                              void* d_out, int out_size) {
    const float* pred = (const float*)d_in[0];
    const unsigned int* targ = (const unsigned int*)d_in[1];
    float* out = (float*)d_out;
    edgeloss_bulk<<<NBLK, TPB>>>(pred, targ, out);
}

// round 16
// speedup vs baseline: 1.0407x; 1.0407x over previous
#include <cuda_runtime.h>
#include <cstdint>

#define Bn 16
#define Cn 19
#define Hn 512
#define Wn 512
#define HWn (Hn * Wn)          // 262144
#define NPIX (Bn * HWn)        // 4194304
#define TPB 256                // one thread per pixel of a half-row
#define HALF (Wn / 2)          // 256 px
#define NBLK (Bn * Hn * 2)     // 16384 blocks = one half-row each
#define SEG_BYTES (HALF * 4)   // 1024 B per channel segment
#define TX_BYTES (Cn * SEG_BYTES)  // 19456 B per block

__device__ double g_acc;       // zero at load; reset by last block each call
__device__ unsigned g_done;    // zero at load; reset by last block each call

__device__ __forceinline__ uint32_t smem_u32(const void* p) {
    uint32_t a;
    asm("{ .reg .u64 t; cvta.to.shared.u64 t, %1; cvt.u32.u64 %0, t; }"
        : "=r"(a) : "l"(p));
    return a;
}

// bulk async copy global->shared, completion via mbarrier transaction bytes
__device__ __forceinline__ void bulk_g2s(uint32_t dst, const void* src,
                                         uint32_t bytes, uint32_t mbar) {
    asm volatile(
        "cp.async.bulk.shared::cluster.global.mbarrier::complete_tx::bytes "
        "[%0], [%1], %2, [%3];"
        :: "r"(dst), "l"(src), "r"(bytes), "r"(mbar) : "memory");
}

// STRIDE compile-time: 2 = int64 targets (read low word), 1 = int32.
template <int STRIDE>
__device__ __forceinline__ bool edge_test(const int* __restrict__ tg,
                                          int b, int h, int w, int& c0) {
    const int* tc = tg + (size_t)(b * HWn + h * Wn + w) * STRIDE;
    c0 = __ldg(tc);
    int d = 0;
    if (h > 0 && h < Hn - 1 && w > 0 && w < Wn - 1) {
#pragma unroll
        for (int dy = -1; dy <= 1; dy++)
#pragma unroll
            for (int dx = -1; dx <= 1; dx++) {
                if (dy == 0 && dx == 0) continue;
                d |= (__ldg(tc + (dy * Wn + dx) * STRIDE) ^ c0);
            }
    } else {
#pragma unroll
        for (int dy = -1; dy <= 1; dy++)
#pragma unroll
            for (int dx = -1; dx <= 1; dx++) {
                if (dy == 0 && dx == 0) continue;
                int hh = h + dy, ww = w + dx;
                if (hh >= 0 && hh < Hn && ww >= 0 && ww < Wn)
                    d |= (__ldg(tc + (dy * Wn + dx) * STRIDE) ^ c0);
            }
    }
    return d != 0;
}

__global__ void __launch_bounds__(TPB, 8)
edgeloss_bulk(const float* __restrict__ pred,
              const unsigned int* __restrict__ tg_raw,
              float* __restrict__ out) {
    const unsigned FULL = 0xFFFFFFFFu;
    __shared__ __align__(128) float s_pred[Cn * HALF];   // 19 KB
    __shared__ __align__(8) unsigned long long s_mbar;
    __shared__ int s_is64;
    __shared__ float s_warp[TPB / 32];

    const int tid = threadIdx.x;
    const uint32_t mbar = smem_u32(&s_mbar);

    // dtype detect: warp 0 checks 64 word-pairs; int32 false-positive p=(1/19)^64
    if (tid < 32) {
        bool ok = true;
#pragma unroll
        for (int k = 0; k < 2; k++) {
            int i = tid + 32 * k;
            ok &= (__ldg(&tg_raw[2 * i + 1]) == 0u) && (__ldg(&tg_raw[2 * i]) < 19u);
        }
        int all_ok = __all_sync(FULL, ok);
        if (tid == 0) s_is64 = all_ok;
    }
    if (tid == 0) {
        asm volatile("mbarrier.init.shared.b64 [%0], %1;"
                     :: "r"(mbar), "r"(1u) : "memory");
    }
    __syncthreads();   // mbarrier init + s_is64 visible

    const int row  = blockIdx.x >> 1;        // which image row
    const int half = blockIdx.x & 1;         // which half of the row
    const int b = row >> 9;                  // / Hn
    const int h = row & (Hn - 1);
    const int w = half * HALF + tid;

    // one thread launches this block's prediction traffic: 19 x 1KB bulk
    // copies. 8 blocks/SM -> 8 outstanding DMA groups per SM keep the
    // LTS/DRAM queues deep while other blocks compute.
    if (tid == 0) {
        asm volatile("mbarrier.arrive.expect_tx.shared.b64 _, [%0], %1;"
                     :: "r"(mbar), "r"((uint32_t)TX_BYTES) : "memory");
        const uint32_t dst0 = smem_u32(s_pred);
        const float* src0 = pred + ((size_t)b * Cn) * HWn
                                 + (size_t)h * Wn + half * HALF;
#pragma unroll
        for (int c = 0; c < Cn; c++)
            bulk_g2s(dst0 + c * SEG_BYTES, src0 + (size_t)c * HWn,
                     SEG_BYTES, mbar);
    }

    // edge mask from targets while the bulk copies fly (L1/L2-hot loads)
    const int* tg = (const int*)tg_raw;
    int c0;
    bool edge;
    if (s_is64) edge = edge_test<2>(tg, b, h, w, c0);
    else        edge = edge_test<1>(tg, b, h, w, c0);

    // wait for prediction data (acquire orders the smem reads below)
    {
        uint32_t done;
        asm volatile(
            "{\n\t.reg .pred p;\n\t"
            "mbarrier.try_wait.parity.acquire.cta.shared::cta.b64 p, [%1], %2;\n\t"
            "selp.b32 %0, 1, 0, p;\n\t}"
            : "=r"(done) : "r"(mbar), "r"(0u) : "memory");
        if (!done) {
            asm volatile(
                "{\n\t.reg .pred P1;\n\t"
                "WL_%=:\n\t"
                "mbarrier.try_wait.parity.acquire.cta.shared::cta.b64 P1, [%0], %1, 0x989680;\n\t"
                "@P1 bra.uni WD_%=;\n\t"
                "bra.uni WL_%=;\n\t"
                "WD_%=:\n\t}"
                :: "r"(mbar), "r"(0u) : "memory");
        }
    }

    // logsumexp from smem: conflict-free LDS (bank = tid%32 for every channel)
    float s0 = 0.0f, s1 = 0.0f;
#pragma unroll
    for (int c = 0; c < Cn; c++) {
        float x = s_pred[c * HALF + tid];
        if (c & 1) s1 += __expf(x); else s0 += __expf(x);
    }
    const float xt = s_pred[c0 * HALF + tid]; // dynamic index: 1 LDS, no conflict

    float ce = __logf(s0 + s1) - xt;
    float val = edge ? (2.0f * ce) : ce;

    // block reduce (8 warps)
#pragma unroll
    for (int off = 16; off > 0; off >>= 1)
        val += __shfl_down_sync(FULL, val, off);
    int lane = tid & 31;
    int wid = tid >> 5;
    if (lane == 0) s_warp[wid] = val;
    __syncthreads();
    if (wid == 0) {
        float bs = (lane < TPB / 32) ? s_warp[lane] : 0.0f;
#pragma unroll
        for (int off = 4; off > 0; off >>= 1)
            bs += __shfl_down_sync(FULL, bs, off);
        if (lane == 0) {
            // FENCE-FREE ordering (no CCTL.IVALL L1 flush): atomics perform at
            // L2; register data-dependence orders g_acc-add before g_done-inc.
            double old = atomicAdd(&g_acc, (double)bs);
            unsigned dep = (unsigned)__double2loint(old);
            asm volatile("and.b32 %0, %0, 0;" : "+r"(dep));  // opaque zero
            unsigned done = atomicAdd(&g_done, 1u + dep);
            if (done == NBLK - 1) {
                double total = atomicAdd(&g_acc, 0.0);
                out[0] = (float)(total / (double)NPIX);
                g_acc = 0.0;               // reset for next graph replay
                g_done = 0u;
            }
        }
    }
}

extern "C" void kernel_launch(void* const* d_in, const int* in_sizes, int n_in,
                              void* d_out, int out_size) {
    const float* pred = (const float*)d_in[0];
    const unsigned int* targ = (const unsigned int*)d_in[1];
    float* out = (float*)d_out;
    edgeloss_bulk<<<NBLK, TPB>>>(pred, targ, out);
}